// round 12
// baseline (speedup 1.0000x reference)
#include <cuda_runtime.h>
#include <math.h>
#include <stdint.h>

#define BATCH 8
#define TOTAL 21824
#define DETS  100
#define IMGF  1024.0f
#define STH   0.2f
#define NMST  0.6f
#define MAXB  128    // per-class bucket capacity (mean ~41, 13-sigma safe)
#define BINN  4096   // quantization bins
#define BCAP  512    // boundary-bin capacity (expected ~16)
#define OCAP  1024   // out contention capacity (expected ~110)
#define SCAP  3328   // compact survivor capacity per batch (max possible 3320)

// ---------------- scratch (all zero at module load; zeroing restored each call) --------
__device__ unsigned long long d_keys[BATCH * TOTAL];
__device__ unsigned long long d_bucket[BATCH * 80 * MAXB];
__device__ int                d_ccnt[BATCH * 80];
__device__ unsigned long long d_sur[BATCH * SCAP];
__device__ int                d_surtot[BATCH];
__device__ int                d_hist[BATCH * 3 * BINN];   // levels 0..2 select hist
__device__ int                d_ohist[BATCH * BINN];      // survivor hist

__device__ __forceinline__ float sigf(float x) { return 1.0f / (1.0f + expf(-x)); }

__device__ __forceinline__ float key_score_hi(unsigned h) {
    unsigned uo = ~h;
    unsigned bits = (uo & 0x80000000u) ? (uo ^ 0x80000000u) : (~uo);
    return __uint_as_float(bits);
}
__device__ __forceinline__ float key_score(unsigned long long key) {
    return key_score_hi((unsigned)(key >> 32));
}
// monotone: higher score -> higher bin; masked (-1) -> bin 0
__device__ __forceinline__ int qbin(unsigned h) {
    float s = key_score_hi(h);
    return (s > 0.0f) ? min(BINN - 1, (int)(s * (float)BINN)) : 0;
}

__device__ __forceinline__ void bucket_push(int b, unsigned long long key) {
    int c = (int)(key & 127ULL);
    int pos = atomicAdd(&d_ccnt[b * 80 + c], 1);
    if (pos < MAXB) d_bucket[(size_t)(b * 80 + c) * MAXB + pos] = key;
}

#define CP_ASYNC16(sm_u32, gptr) \
    asm volatile("cp.async.cg.shared.global [%0], [%1], 16;" :: "r"(sm_u32), "l"(gptr))
#define CP_COMMIT() asm volatile("cp.async.commit_group;")

// ---------------- K1: cp.async 2-tile pipelined score + argmax + level histogram -------
// key = (~orderable(score))<<32 | idx<<7 | label : ascending == (score desc, idx asc);
// keys globally distinct; matches jax.lax.top_k stable tie order.
#define SCORE_SMEM (81920 + 1024)   // 2 tiles of 128 anchors x 320B + 256 ctr floats

__global__ __launch_bounds__(512) void k_score(const float* __restrict__ logits,
                                               const float* __restrict__ ctr) {
    extern __shared__ float4 s4[];   // [2 * 2560] float4, then 256 ctr floats
    float* ctr_s = (float*)((char*)s4 + 81920);
    int tid = threadIdx.x;
    size_t tile0 = (size_t)blockIdx.x * 2;
    const float4* g = reinterpret_cast<const float4*>(logits) + tile0 * 2560;
    unsigned sbase = (unsigned)__cvta_generic_to_shared(s4);

    // group 0: stage-0 logits + all ctr. group 1: stage-1 logits.
#pragma unroll
    for (int i = 0; i < 5; i++) {
        int off = i * 512 + tid;
        CP_ASYNC16(sbase + off * 16, g + off);
    }
    if (tid < 64) CP_ASYNC16(sbase + 81920 + tid * 16, ctr + tile0 * 128 + tid * 4);
    CP_COMMIT();
#pragma unroll
    for (int i = 0; i < 5; i++) {
        int off = 2560 + i * 512 + tid;
        CP_ASYNC16(sbase + off * 16, g + off);
    }
    CP_COMMIT();

    int la = tid >> 2;   // local anchor 0..127
    int q  = tid & 3;    // quarter: cols 20q..20q+19

#pragma unroll
    for (int s = 0; s < 2; s++) {
        if (s == 0) asm volatile("cp.async.wait_group 1;");
        else        asm volatile("cp.async.wait_group 0;");
        __syncthreads();

        const float4* rowq = s4 + s * 2560 + la * 20 + q * 5;
        float best = -1e30f;
        int bi = 0;
#pragma unroll
        for (int i = 0; i < 5; i++) {  // strict > keeps first-max within lane
            float4 v = rowq[i];
            int cb = q * 20 + i * 4;
            if (v.x > best) { best = v.x; bi = cb + 0; }
            if (v.y > best) { best = v.y; bi = cb + 1; }
            if (v.z > best) { best = v.z; bi = cb + 2; }
            if (v.w > best) { best = v.w; bi = cb + 3; }
        }
#pragma unroll
        for (int o = 2; o >= 1; o >>= 1) {  // tie -> lower column (= first occurrence)
            float ov = __shfl_down_sync(0xFFFFFFFFu, best, o);
            int   oc = __shfl_down_sync(0xFFFFFFFFu, bi, o);
            if (ov > best || (ov == best && oc < bi)) { best = ov; bi = oc; }
        }
        if (q == 0) {
            int ga = (int)(tile0 + s) * 128 + la;
            float sc = sqrtf(sigf(best) * sigf(ctr_s[s * 128 + la]));
            float smv = (sc > STH) ? sc : -1.0f;
            unsigned u = __float_as_uint(smv);
            u ^= (u & 0x80000000u) ? 0xFFFFFFFFu : 0x80000000u;
            unsigned h = ~u;
            int b = ga / TOTAL;
            int i_loc = ga - b * TOTAL;
            d_keys[ga] = ((unsigned long long)h << 32) |
                         ((unsigned)(i_loc << 7) | (unsigned)bi);
            int lvl = (i_loc < 16384) ? 0 : (i_loc < 20480) ? 1 : (i_loc < 21504) ? 2 : -1;
            if (lvl >= 0) atomicAdd(&d_hist[(b * 3 + lvl) * BINN + qbin(h)], 1);
        }
        __syncthreads();   // before next stage reuses nothing, but keeps ctr_s safe
    }
}

// ---------------- K2: per (batch, level) exact top-k; hist prebuilt by k_score ---------
// Scan global hist -> boundary bin Q + kneed; ONE sweep: push bins>Q, collect boundary;
// exact in-bin rank pushes the kneed smallest boundary keys. Exact incl. ties.
__global__ __launch_bounds__(1024, 1) void k_select() {
    const int LOFF[5] = {0, 16384, 20480, 21504, 21760};
    const int LN[5]   = {16384, 4096, 1024, 256, 64};
    const int LK[5]   = {1000, 1000, 1000, 256, 64};

    int b = blockIdx.x / 5, lvl = blockIdx.x % 5;
    int off = LOFF[lvl], n = LN[lvl], k = LK[lvl];
    int tid = threadIdx.x, lane = tid & 31, wid = tid >> 5;
    const unsigned long long* kp = d_keys + b * TOTAL + off;

    if (k >= n) {  // levels 3,4: everything selected
        for (int i = tid; i < n; i += 1024) bucket_push(b, kp[i]);
        return;
    }

    __shared__ unsigned long long binkeys[BCAP];
    __shared__ int warpsum[32];
    __shared__ int sh_Q, sh_kneed, sh_bc;
    if (tid == 0) sh_bc = 0;
    __syncthreads();

    const int* hist = d_hist + (b * 3 + lvl) * BINN;

    // descending-bin cumulative scan (4 bins/thread): boundary bin Q, kneed
    {
        int vv[4], mysum = 0;
#pragma unroll
        for (int j = 0; j < 4; j++) { vv[j] = hist[BINN - 1 - (tid * 4 + j)]; mysum += vv[j]; }
        int inc = mysum;
#pragma unroll
        for (int o = 1; o < 32; o <<= 1) { int t2 = __shfl_up_sync(0xFFFFFFFFu, inc, o); if (lane >= o) inc += t2; }
        if (lane == 31) warpsum[wid] = inc;
        __syncthreads();
        if (tid < 32) {
            int w = warpsum[tid], s = w;
#pragma unroll
            for (int o = 1; o < 32; o <<= 1) { int t2 = __shfl_up_sync(0xFFFFFFFFu, s, o); if (tid >= o) s += t2; }
            warpsum[tid] = s - w;  // exclusive
        }
        __syncthreads();
        int c = warpsum[wid] + inc - mysum;
#pragma unroll
        for (int j = 0; j < 4; j++) {
            if (c < k && c + vv[j] >= k) {
                sh_Q = BINN - 1 - (tid * 4 + j);
                sh_kneed = k - c;
            }
            c += vv[j];
        }
    }
    __syncthreads();
    int Q = sh_Q, kneed = sh_kneed;

    // single sweep: push bins > Q; collect boundary bin
    for (int i = tid; i < n; i += 1024) {
        unsigned long long key = kp[i];
        int q = qbin((unsigned)(key >> 32));
        if (q > Q) {
            bucket_push(b, key);
        } else if (q == Q) {
            int p = atomicAdd(&sh_bc, 1);
            if (p < BCAP) binkeys[p] = key;
        }
    }
    __syncthreads();
    int C = min(sh_bc, BCAP);

    // exact in-bin rank; push the kneed smallest boundary keys (keys distinct)
    for (int t = tid; t < C; t += 1024) {
        unsigned long long mk = binkeys[t];
        int r = 0;
        for (int j2 = 0; j2 < C; j2++) r += (binkeys[j2] < mk);
        if (r < kneed) bucket_push(b, mk);
    }
}

// ---------------- K3: one warp per (batch,class): sort, NMS, append + survivor hist ----
__global__ __launch_bounds__(32) void k_nms(const float* __restrict__ reg,
                                            const float* __restrict__ anchors) {
    int bc = blockIdx.x, b = bc / 80;
    __shared__ unsigned long long kb[MAXB];
    __shared__ float4 bxs[MAXB];
    __shared__ float  ar[MAXB], sv[MAXB];
    __shared__ unsigned char rm[MAXB];
    int lane = threadIdx.x;

    // restore d_hist to zero for the next call (select is done with it)
    {
        const int totalH = BATCH * 3 * BINN;
        int per = (totalH + 639) / 640;   // grid is 640
        int s0 = bc * per, s1 = min(s0 + per, totalH);
        for (int i = s0 + lane; i < s1; i += 32) d_hist[i] = 0;
    }

    int cnt = min(d_ccnt[bc], MAXB);
    if (cnt == 0) return;
    for (int i = lane; i < cnt; i += 32)
        kb[i] = d_bucket[(size_t)bc * MAXB + i];
    __syncwarp();

    // warp bitonic sort ascending (== score desc, idx asc)
    int m = 2; while (m < cnt) m <<= 1;
    for (int i = lane; i < m; i += 32) if (i >= cnt) kb[i] = ~0ULL;
    __syncwarp();
    for (int kk = 2; kk <= m; kk <<= 1)
        for (int jj = kk >> 1; jj > 0; jj >>= 1) {
            for (int cc = lane; cc < (m >> 1); cc += 32) {
                int i1 = ((cc & ~(jj - 1)) << 1) | (cc & (jj - 1));
                int l1 = i1 | jj;
                bool up = ((i1 & kk) == 0);
                unsigned long long a2 = kb[i1], d2 = kb[l1];
                if ((a2 > d2) == up) { kb[i1] = d2; kb[l1] = a2; }
            }
            __syncwarp();
        }

    // decode
    for (int i = lane; i < cnt; i += 32) {
        unsigned long long key = kb[i];
        int idx = (int)((key >> 7) & 0x7FFFULL);
        sv[i] = key_score(key);
        rm[i] = 0;
        float4 an = reinterpret_cast<const float4*>(anchors)[idx];
        float cx = (an.x + an.z) * 0.5f, cy = (an.y + an.w) * 0.5f;
        float4 r = reinterpret_cast<const float4*>(reg)[(size_t)b * TOTAL + idx];
        float x1 = fminf(fmaxf(cx - r.x, 0.0f), IMGF);
        float y1 = fminf(fmaxf(cy - r.y, 0.0f), IMGF);
        float x2 = fminf(fmaxf(cx + r.z, 0.0f), IMGF);
        float y2 = fminf(fmaxf(cy + r.w, 0.0f), IMGF);
        bxs[i] = make_float4(x1, y1, x2, y2);
        ar[i] = fmaxf(x2 - x1, 0.0f) * fmaxf(y2 - y1, 0.0f);
    }
    __syncwarp();

    // greedy NMS (masked sort last; suppressed never suppress)
    for (int i = 0; i < cnt; i++) {
        if (sv[i] <= STH) break;
        if (rm[i]) continue;
        float4 bi = bxs[i];
        float ai = ar[i];
        for (int j = i + 1 + lane; j < cnt; j += 32) {
            float4 bj = bxs[j];
            float iw = fmaxf(fminf(bi.z, bj.z) - fmaxf(bi.x, bj.x), 0.0f);
            float ih = fmaxf(fminf(bi.w, bj.w) - fmaxf(bi.y, bj.y), 0.0f);
            float inter = iw * ih;
            float iou = inter / fmaxf(ai + ar[j] - inter, 1e-9f);
            if (iou > NMST) rm[j] = 1;
        }
        __syncwarp();
    }

    // append survivors (per-class cap DETS) + survivor histogram
    int wcnt = 0;
    for (int base = 0; base < cnt; base += 32) {
        int i = base + lane;
        bool acc = (i < cnt) && (sv[i] > STH) && !rm[i];
        unsigned bal = __ballot_sync(0xFFFFFFFFu, acc);
        int nb = __popc(bal);
        int nTake = min(nb, max(0, DETS - wcnt));
        int pos = 0;
        if (lane == 0 && nTake > 0) pos = atomicAdd(&d_surtot[b], nTake);
        pos = __shfl_sync(0xFFFFFFFFu, pos, 0);
        int rk = __popc(bal & ((1u << lane) - 1));
        if (acc && rk < nTake && pos + rk < SCAP) {
            d_sur[(size_t)b * SCAP + pos + rk] = kb[i];
            atomicAdd(&d_ohist[b * BINN + qbin((unsigned)(kb[i] >> 32))], 1);
        }
        wcnt += nb;
    }
}

// ---------------- K4: per-batch top-100; survivor hist prebuilt by k_nms ----------------
__global__ __launch_bounds__(1024, 1) void k_out(const float* __restrict__ reg,
                                                 const float* __restrict__ anchors,
                                                 float* __restrict__ out) {
    __shared__ unsigned long long cont[OCAP];
    __shared__ unsigned long long win[DETS];
    __shared__ int warpsum[32];
    __shared__ int sh_cc, sh_Q;

    int b = blockIdx.x, tid = threadIdx.x, lane = tid & 31, wid = tid >> 5;

    int S = min(d_surtot[b], SCAP);
    int ns = min(DETS, S);
    if (tid == 0) { sh_cc = 0; sh_Q = 0; }
    __syncthreads();

    const int* hist = d_ohist + b * BINN;

    if (ns > 0) {
        // descending-bin scan: first bin where cum >= ns
        int vv[4], mysum = 0;
#pragma unroll
        for (int j = 0; j < 4; j++) { vv[j] = hist[BINN - 1 - (tid * 4 + j)]; mysum += vv[j]; }
        int inc = mysum;
#pragma unroll
        for (int o = 1; o < 32; o <<= 1) { int t2 = __shfl_up_sync(0xFFFFFFFFu, inc, o); if (lane >= o) inc += t2; }
        if (lane == 31) warpsum[wid] = inc;
        __syncthreads();
        if (tid < 32) {
            int w = warpsum[tid], s = w;
#pragma unroll
            for (int o = 1; o < 32; o <<= 1) { int t2 = __shfl_up_sync(0xFFFFFFFFu, s, o); if (tid >= o) s += t2; }
            warpsum[tid] = s - w;
        }
        __syncthreads();
        int c = warpsum[wid] + inc - mysum;
#pragma unroll
        for (int j = 0; j < 4; j++) {
            if (c < ns && c + vv[j] >= ns) sh_Q = BINN - 1 - (tid * 4 + j);
            c += vv[j];
        }
        __syncthreads();
        int Q = sh_Q;

        // single sweep: contention = all bins >= Q (superset of top-ns)
        for (int i = tid; i < S; i += 1024) {
            unsigned long long key = d_sur[(size_t)b * SCAP + i];
            if (qbin((unsigned)(key >> 32)) >= Q) {
                int p = atomicAdd(&sh_cc, 1);
                if (p < OCAP) cont[p] = key;
            }
        }
        __syncthreads();
        int C = min(sh_cc, OCAP);

        // exact rank within contention == global rank for r < ns
        for (int t = tid; t < C; t += 1024) {
            unsigned long long mk = cont[t];
            int r = 0;
            for (int q2 = 0; q2 < C; q2++) r += (cont[q2] < mk);
            if (r < ns) win[r] = mk;
        }
    }
    __syncthreads();

    // decode + write
    for (int t = tid; t < DETS; t += 1024) {
        float* ob = out + ((size_t)b * DETS + t) * 4;
        if (t >= ns) {
            ob[0] = 0.0f; ob[1] = 0.0f; ob[2] = 0.0f; ob[3] = 0.0f;
            out[BATCH * DETS * 4 + b * DETS + t] = 0.0f;
            out[BATCH * DETS * 5 + b * DETS + t] = -1.0f;
        } else {
            unsigned long long key = win[t];
            int idx = (int)((key >> 7) & 0x7FFFULL);
            float4 an = reinterpret_cast<const float4*>(anchors)[idx];
            float cx = (an.x + an.z) * 0.5f, cy = (an.y + an.w) * 0.5f;
            float4 r = reinterpret_cast<const float4*>(reg)[(size_t)b * TOTAL + idx];
            float x1 = fminf(fmaxf(cx - r.x, 0.0f), IMGF);
            float y1 = fminf(fmaxf(cy - r.y, 0.0f), IMGF);
            float x2 = fminf(fmaxf(cx + r.z, 0.0f), IMGF);
            float y2 = fminf(fmaxf(cy + r.w, 0.0f), IMGF);
            ob[0] = x1; ob[1] = y1; ob[2] = x2; ob[3] = y2;
            out[BATCH * DETS * 4 + b * DETS + t] = key_score(key);
            out[BATCH * DETS * 5 + b * DETS + t] = (float)(key & 127ULL);
        }
    }
    __syncthreads();

    // restore per-batch scratch to zero for the next call
    for (int i = tid; i < BINN; i += 1024) d_ohist[b * BINN + i] = 0;
    for (int i = tid; i < 80; i += 1024) d_ccnt[b * 80 + i] = 0;
    if (tid == 0) d_surtot[b] = 0;
}

// ---------------- launch ----------------
extern "C" void kernel_launch(void* const* d_in, const int* in_sizes, int n_in,
                              void* d_out, int out_size) {
    const float* logits  = (const float*)d_in[0];  // (8, 21824, 80)
    const float* reg     = (const float*)d_in[1];  // (8, 21824, 4)
    const float* ctr     = (const float*)d_in[2];  // (8, 21824, 1)
    const float* anchors = (const float*)d_in[3];  // (21824, 4)
    float* out = (float*)d_out;

    cudaFuncSetAttribute(k_score, cudaFuncAttributeMaxDynamicSharedMemorySize, SCORE_SMEM);

    k_score<<<(BATCH * TOTAL) / 256, 512, SCORE_SMEM>>>(logits, ctr);
    k_select<<<BATCH * 5, 1024>>>();
    k_nms<<<BATCH * 80, 32>>>(reg, anchors);
    k_out<<<BATCH, 1024>>>(reg, anchors, out);
}